// round 9
// baseline (speedup 1.0000x reference)
#include <cuda_runtime.h>
#include <cuda_bf16.h>
#include <cstdint>

// Complex attention, tensor cores via mma.sync bf16 3-term split.
// R9: QK persistent-kt with double-buffered K (1 CTA/SM, deep pipeline);
//     AV with direct-gmem A fragments + double-buffered V (2 CTAs/SM).

#define NKT 2
typedef unsigned long long u64;
typedef uint32_t u32;

__device__ float g_ar[(size_t)64 * 1024 * 1024];   // 256 MB
__device__ float g_ai[(size_t)64 * 1024 * 1024];   // 256 MB
__device__ float g_pmin[64 * 1024 * NKT];
__device__ float g_pmax[64 * 1024 * NKT];
__device__ float g_mn[64 * 1024];
__device__ float g_inv[64 * 1024];

__device__ __forceinline__ u32 smem_u32(const void* p) {
    u32 a;
    asm("{ .reg .u64 t; cvta.to.shared.u64 t, %1; cvt.u32.u64 %0, t; }"
        : "=r"(a) : "l"(p));
    return a;
}

#define SW128(x) ((x) ^ (((x) >> 3) & 0x70))
#define SWZ64(x) ((x) ^ (((x) >> 2) & 0x70))
#define NEGS 0x80008000u
#define TB16 16384
#define TB8  8192
#define VB   4096

__device__ __forceinline__ void ldmx4(u32* r, u32 a) {
    asm volatile("ldmatrix.sync.aligned.m8n8.x4.shared.b16 {%0,%1,%2,%3}, [%4];"
        : "=r"(r[0]), "=r"(r[1]), "=r"(r[2]), "=r"(r[3]) : "r"(a));
}
__device__ __forceinline__ void ldmx2(u32* r, u32 a) {
    asm volatile("ldmatrix.sync.aligned.m8n8.x2.shared.b16 {%0,%1}, [%2];"
        : "=r"(r[0]), "=r"(r[1]) : "r"(a));
}
__device__ __forceinline__ void ldmx2t(u32* r, u32 a) {
    asm volatile("ldmatrix.sync.aligned.m8n8.x2.trans.shared.b16 {%0,%1}, [%2];"
        : "=r"(r[0]), "=r"(r[1]) : "r"(a));
}
__device__ __forceinline__ void mma16816(float* c, const u32* a, const u32* b) {
    asm volatile("mma.sync.aligned.m16n8k16.row.col.f32.bf16.bf16.f32 "
        "{%0,%1,%2,%3}, {%4,%5,%6,%7}, {%8,%9}, {%0,%1,%2,%3};"
        : "+f"(c[0]), "+f"(c[1]), "+f"(c[2]), "+f"(c[3])
        : "r"(a[0]), "r"(a[1]), "r"(a[2]), "r"(a[3]), "r"(b[0]), "r"(b[1]));
}

// fp32 pair -> bf16 hi/lo pairs, SW128 layout (128B rows).
__device__ __forceinline__ void st_split2(char* hi, char* lo, int row, int cp, float2 v) {
    __nv_bfloat162 h = __float22bfloat162_rn(v);
    float2 hf = __bfloat1622float2(h);
    __nv_bfloat162 l = __float22bfloat162_rn(make_float2(v.x - hf.x, v.y - hf.y));
    u32 off = SW128((u32)(row * 128 + cp * 4));
    *(u32*)(hi + off) = *(u32*)&h;
    *(u32*)(lo + off) = *(u32*)&l;
}
// 64B-row variant for AV's V tiles.
__device__ __forceinline__ void st_split2v(char* hi, char* lo, int row, int dp, float2 v) {
    __nv_bfloat162 h = __float22bfloat162_rn(v);
    float2 hf = __bfloat1622float2(h);
    __nv_bfloat162 l = __float22bfloat162_rn(make_float2(v.x - hf.x, v.y - hf.y));
    u32 off = SWZ64((u32)(row * 64 + dp * 4));
    *(u32*)(hi + off) = *(u32*)&h;
    *(u32*)(lo + off) = *(u32*)&l;
}
__device__ __forceinline__ u32 bf2hi(float2 v) {
    __nv_bfloat162 h = __float22bfloat162_rn(v);
    return *(u32*)&h;
}
__device__ __forceinline__ u32 bf2lo(float2 v, u32 hbits) {
    __nv_bfloat162 h = *(__nv_bfloat162*)&hbits;
    float2 hf = __bfloat1622float2(h);
    __nv_bfloat162 l = __float22bfloat162_rn(make_float2(v.x - hf.x, v.y - hf.y));
    return *(u32*)&l;
}

// ---------------------------------------------------------------------------
// K1: QK persistent over 8 k-tiles. Q resident (64KB), K double-buffered
// (2 x 32KB). 8 warps (4m x 2n), warp tile 32q x 32k per k-tile.
// attn_r = qr.kr - qi.ki ; attn_i = qr.ki + qi.kr (3-term bf16 splits)
// ---------------------------------------------------------------------------
__global__ __launch_bounds__(256, 1) void qk_kernel(
    const float* __restrict__ qr, const float* __restrict__ qi,
    const float* __restrict__ kr, const float* __restrict__ ki)
{
    extern __shared__ __align__(128) char sm[];
    char* s_qrh = sm;
    char* s_qrl = s_qrh + TB16;
    char* s_qih = s_qrl + TB16;
    char* s_qil = s_qih + TB16;
    char* s_kbuf = s_qil + TB16;          // 2 x (4 x TB8)
    __shared__ float sMin[128][2], sMax[128][2];

    const int tid = threadIdx.x, wid = tid >> 5, lane = tid & 31;
    const int half = blockIdx.x, qt = blockIdx.y, bh = blockIdx.z;
    const int kt0 = half << 3;
    const int cp = tid & 31, r0 = tid >> 5;

    // ---- Q fill ----
    {
        const size_t qbase = ((size_t)((bh << 10) + (qt << 7))) << 6;
        #pragma unroll
        for (int it = 0; it < 16; ++it) {
            int row = r0 + (it << 3);
            float2 a = *(const float2*)(qr + qbase + (row << 6) + cp * 2);
            float2 b = *(const float2*)(qi + qbase + (row << 6) + cp * 2);
            a.x *= 0.125f; a.y *= 0.125f;
            b.x *= 0.125f; b.y *= 0.125f;
            st_split2(s_qrh, s_qrl, row, cp, a);
            st_split2(s_qih, s_qil, row, cp, b);
        }
    }
    // ---- K first tile into buffer 0 ----
    {
        const size_t kbase = ((size_t)((bh << 10) + (kt0 << 6))) << 6;
        #pragma unroll
        for (int it = 0; it < 8; ++it) {
            int row = r0 + (it << 3);
            float2 c = *(const float2*)(kr + kbase + (row << 6) + cp * 2);
            float2 d = *(const float2*)(ki + kbase + (row << 6) + cp * 2);
            st_split2(s_kbuf, s_kbuf + TB8, row, cp, c);
            st_split2(s_kbuf + 2 * TB8, s_kbuf + 3 * TB8, row, cp, d);
        }
    }
    __syncthreads();

    const int wm = wid >> 1, wn = wid & 1;
    const int g = lane >> 2, tg = lane & 3;
    const u32 uq0 = smem_u32(s_qrh), uq1 = smem_u32(s_qrl);
    const u32 uq2 = smem_u32(s_qih), uq3 = smem_u32(s_qil);
    const u32 a_row = (u32)(wm * 32 + (lane & 15));
    const u32 a_cb  = (u32)((lane >> 4) * 16);
    const u32 b_row = (u32)(wn * 32 + (lane & 7));
    const u32 b_cb  = (u32)(((lane >> 3) & 1) * 16);

    float rmn[4] = {3.4e38f, 3.4e38f, 3.4e38f, 3.4e38f};
    float rmx[4] = {0.f, 0.f, 0.f, 0.f};
    float2 pKr[8], pKi[8];

    #pragma unroll 1
    for (int t = 0; t < 8; ++t) {
        const int kt = kt0 + t;
        const u32 ukb = smem_u32(s_kbuf + (t & 1) * (4 * TB8));

        // prefetch next K tile into registers (LDGs overlap the MMAs below)
        if (t < 7) {
            const size_t kbase = ((size_t)((bh << 10) + ((kt + 1) << 6))) << 6;
            #pragma unroll
            for (int it = 0; it < 8; ++it) {
                int row = r0 + (it << 3);
                pKr[it] = *(const float2*)(kr + kbase + (row << 6) + cp * 2);
                pKi[it] = *(const float2*)(ki + kbase + (row << 6) + cp * 2);
            }
        }

        float accR[2][4][4] = {}, accI[2][4][4] = {};
        #pragma unroll
        for (int kb = 0; kb < 4; ++kb) {
            u32 Aqrh[2][4], Aqrl[2][4], Aqih[2][4], Aqil[2][4];
            #pragma unroll
            for (int mb = 0; mb < 2; ++mb) {
                u32 off = SW128((a_row + mb * 16) * 128 + kb * 32 + a_cb);
                ldmx4(Aqrh[mb], uq0 + off);
                ldmx4(Aqrl[mb], uq1 + off);
                ldmx4(Aqih[mb], uq2 + off);
                ldmx4(Aqil[mb], uq3 + off);
            }
            #pragma unroll
            for (int nb = 0; nb < 4; ++nb) {
                u32 off = SW128((b_row + nb * 8) * 128 + kb * 32 + b_cb);
                u32 Bkrh[2], Bkrl[2], Bkih[2], Bkil[2];
                ldmx2(Bkrh, ukb + off);
                ldmx2(Bkrl, ukb + TB8 + off);
                ldmx2(Bkih, ukb + 2 * TB8 + off);
                ldmx2(Bkil, ukb + 3 * TB8 + off);
                u32 Bknh[2] = { Bkih[0] ^ NEGS, Bkih[1] ^ NEGS };
                u32 Bknl[2] = { Bkil[0] ^ NEGS, Bkil[1] ^ NEGS };
                #pragma unroll
                for (int mb = 0; mb < 2; ++mb) {
                    mma16816(accR[mb][nb], Aqrh[mb], Bkrh);
                    mma16816(accR[mb][nb], Aqrh[mb], Bkrl);
                    mma16816(accR[mb][nb], Aqrl[mb], Bkrh);
                    mma16816(accR[mb][nb], Aqih[mb], Bknh);
                    mma16816(accR[mb][nb], Aqih[mb], Bknl);
                    mma16816(accR[mb][nb], Aqil[mb], Bknh);
                    mma16816(accI[mb][nb], Aqrh[mb], Bkih);
                    mma16816(accI[mb][nb], Aqrh[mb], Bkil);
                    mma16816(accI[mb][nb], Aqrl[mb], Bkih);
                    mma16816(accI[mb][nb], Aqih[mb], Bkrh);
                    mma16816(accI[mb][nb], Aqih[mb], Bkrl);
                    mma16816(accI[mb][nb], Aqil[mb], Bkrh);
                }
            }
        }

        // stash prefetched K into the other buffer
        if (t < 7) {
            char* nb_ = s_kbuf + ((t + 1) & 1) * (4 * TB8);
            #pragma unroll
            for (int it = 0; it < 8; ++it) {
                int row = r0 + (it << 3);
                st_split2(nb_, nb_ + TB8, row, cp, pKr[it]);
                st_split2(nb_ + 2 * TB8, nb_ + 3 * TB8, row, cp, pKi[it]);
            }
        }

        // epilogue: store attn + accumulate row mag^2 min/max in registers
        #pragma unroll
        for (int mb = 0; mb < 2; ++mb)
            #pragma unroll
            for (int hf = 0; hf < 2; ++hf) {
                int rl = wm * 32 + mb * 16 + hf * 8 + g;
                size_t ab = (((size_t)((bh << 10) + (qt << 7) + rl)) << 10)
                          + (kt << 6) + wn * 32 + tg * 2;
                float mn = rmn[mb * 2 + hf], mx = rmx[mb * 2 + hf];
                #pragma unroll
                for (int nb = 0; nb < 4; ++nb) {
                    float x0 = accR[mb][nb][hf * 2], x1 = accR[mb][nb][hf * 2 + 1];
                    float y0 = accI[mb][nb][hf * 2], y1 = accI[mb][nb][hf * 2 + 1];
                    *(float2*)(g_ar + ab + nb * 8) = make_float2(x0, x1);
                    *(float2*)(g_ai + ab + nb * 8) = make_float2(y0, y1);
                    float m0 = x0 * x0 + y0 * y0, m1 = x1 * x1 + y1 * y1;
                    mn = fminf(mn, fminf(m0, m1));
                    mx = fmaxf(mx, fmaxf(m0, m1));
                }
                rmn[mb * 2 + hf] = mn; rmx[mb * 2 + hf] = mx;
            }
        __syncthreads();
    }

    // final min/max: shfl over the k-lane quad, combine the two wn warps
    #pragma unroll
    for (int s = 0; s < 4; ++s) {
        rmn[s] = fminf(rmn[s], __shfl_xor_sync(0xffffffffu, rmn[s], 1));
        rmn[s] = fminf(rmn[s], __shfl_xor_sync(0xffffffffu, rmn[s], 2));
        rmx[s] = fmaxf(rmx[s], __shfl_xor_sync(0xffffffffu, rmx[s], 1));
        rmx[s] = fmaxf(rmx[s], __shfl_xor_sync(0xffffffffu, rmx[s], 2));
    }
    if (tg == 0) {
        #pragma unroll
        for (int mb = 0; mb < 2; ++mb)
            #pragma unroll
            for (int hf = 0; hf < 2; ++hf) {
                int rl = wm * 32 + mb * 16 + hf * 8 + g;
                sMin[rl][wn] = rmn[mb * 2 + hf];
                sMax[rl][wn] = rmx[mb * 2 + hf];
            }
    }
    __syncthreads();
    if (tid < 128) {
        float mn = fminf(sMin[tid][0], sMin[tid][1]);
        float mx = fmaxf(sMax[tid][0], sMax[tid][1]);
        int row = (qt << 7) + tid;
        g_pmin[(((bh << 10) + row) << 1) + half] = mn;
        g_pmax[(((bh << 10) + row) << 1) + half] = mx;
    }
}

// ---------------------------------------------------------------------------
// K2: reduce 2 partials/row -> mn = sqrt(min m2), inv = 1/(mx - mn).
// ---------------------------------------------------------------------------
__global__ void minmax_kernel()
{
    int r = blockIdx.x * 256 + threadIdx.x;   // 65536 rows
    float mn2 = fminf(g_pmin[r * 2], g_pmin[r * 2 + 1]);
    float mx2 = fmaxf(g_pmax[r * 2], g_pmax[r * 2 + 1]);
    float mnv = sqrtf(mn2), mxv = sqrtf(mx2);
    g_mn[r] = mnv;
    g_inv[r] = 1.0f / (mxv - mnv);
}

// ---------------------------------------------------------------------------
// K3: AV. CTA tile 128q x 32d (dh selects d half), 8 warps x 16q each.
// A fragments built directly from gmem (normalize in regs, no A smem).
// V double-buffered in smem (64B rows, custom swizzle). 16 k-chunks of 64.
// out_r = ar.vr - ai.vi ; out_i = ar.vi + ai.vr
// ---------------------------------------------------------------------------
__global__ __launch_bounds__(256, 2) void av_kernel(
    const float* __restrict__ vr, const float* __restrict__ vi,
    float* __restrict__ out)
{
    extern __shared__ __align__(128) char sm[];   // 2 bufs x 4 arrays x 4KB

    const int tid = threadIdx.x, wid = tid >> 5, lane = tid & 31;
    const int g = lane >> 2, tg = lane & 3;
    const int dh = blockIdx.x, qt = blockIdx.y, bh = blockIdx.z;

    const int q0 = (qt << 7) + (wid << 4);
    const int gr0 = q0 + g, gr1 = q0 + 8 + g;
    const float inv0 = g_inv[(bh << 10) + gr0];
    const float mni0 = g_mn[(bh << 10) + gr0] * inv0;
    const float inv1 = g_inv[(bh << 10) + gr1];
    const float mni1 = g_mn[(bh << 10) + gr1] * inv1;
    const size_t arow0 = ((size_t)((bh << 10) + gr0)) << 10;
    const size_t arow1 = ((size_t)((bh << 10) + gr1)) << 10;

    const int dp = tid & 15, kr0 = tid >> 4;
    const size_t vbase = ((size_t)(bh << 10)) << 6;

    // ---- prologue: V chunk 0 + A(0,0) ----
    float2 pVr[4], pVi[4];
    #pragma unroll
    for (int it = 0; it < 4; ++it) {
        int k = kr0 + (it << 4);
        size_t vo = vbase + ((size_t)k << 6) + (dh << 5) + dp * 2;
        pVr[it] = *(const float2*)(vr + vo);
        pVi[it] = *(const float2*)(vi + vo);
    }
    #pragma unroll
    for (int it = 0; it < 4; ++it) {
        int k = kr0 + (it << 4);
        st_split2v(sm, sm + VB, k, dp, pVr[it]);
        st_split2v(sm + 2 * VB, sm + 3 * VB, k, dp, pVi[it]);
    }
    float2 rAr[2][4], rAi[2][4];
    {
        int k0 = tg * 2;
        rAr[0][0] = *(const float2*)(g_ar + arow0 + k0);
        rAr[0][1] = *(const float2*)(g_ar + arow1 + k0);
        rAr[0][2] = *(const float2*)(g_ar + arow0 + k0 + 8);
        rAr[0][3] = *(const float2*)(g_ar + arow1 + k0 + 8);
        rAi[0][0] = *(const float2*)(g_ai + arow0 + k0);
        rAi[0][1] = *(const float2*)(g_ai + arow1 + k0);
        rAi[0][2] = *(const float2*)(g_ai + arow0 + k0 + 8);
        rAi[0][3] = *(const float2*)(g_ai + arow1 + k0 + 8);
    }
    __syncthreads();

    float accR[4][4] = {}, accI[4][4] = {};

    #pragma unroll 1
    for (int c = 0; c < 16; ++c) {
        // V prefetch for next chunk
        if (c < 15) {
            #pragma unroll
            for (int it = 0; it < 4; ++it) {
                int k = ((c + 1) << 6) + kr0 + (it << 4);
                size_t vo = vbase + ((size_t)k << 6) + (dh << 5) + dp * 2;
                pVr[it] = *(const float2*)(vr + vo);
                pVi[it] = *(const float2*)(vi + vo);
            }
        }
        const u32 uvb = smem_u32(sm + (c & 1) * (4 * VB));
        #pragma unroll
        for (int kb = 0; kb < 4; ++kb) {
            const int cur = kb & 1;
            // A prefetch one kb ahead (wraps to next chunk at kb==3)
            if (!(c == 15 && kb == 3)) {
                int nc = (kb == 3) ? c + 1 : c;
                int nkb = (kb == 3) ? 0 : kb + 1;
                int k0 = (nc << 6) + (nkb << 4) + tg * 2;
                rAr[cur ^ 1][0] = *(const float2*)(g_ar + arow0 + k0);
                rAr[cur ^ 1][1] = *(const float2*)(g_ar + arow1 + k0);
                rAr[cur ^ 1][2] = *(const float2*)(g_ar + arow0 + k0 + 8);
                rAr[cur ^ 1][3] = *(const float2*)(g_ar + arow1 + k0 + 8);
                rAi[cur ^ 1][0] = *(const float2*)(g_ai + arow0 + k0);
                rAi[cur ^ 1][1] = *(const float2*)(g_ai + arow1 + k0);
                rAi[cur ^ 1][2] = *(const float2*)(g_ai + arow0 + k0 + 8);
                rAi[cur ^ 1][3] = *(const float2*)(g_ai + arow1 + k0 + 8);
            }
            // normalize + split current A into mma fragments
            u32 arh[4], arl[4], aih[4], ail[4];
            #pragma unroll
            for (int p = 0; p < 4; ++p) {
                float2 x = rAr[cur][p], y = rAi[cur][p];
                float inv = (p & 1) ? inv1 : inv0;
                float mni = (p & 1) ? mni1 : mni0;
                float f0 = inv - mni * rsqrtf(x.x * x.x + y.x * y.x);
                float f1 = inv - mni * rsqrtf(x.y * x.y + y.y * y.y);
                float2 a2 = make_float2(x.x * f0, x.y * f1);
                float2 b2 = make_float2(y.x * f0, y.y * f1);
                arh[p] = bf2hi(a2); arl[p] = bf2lo(a2, arh[p]);
                aih[p] = bf2hi(b2); ail[p] = bf2lo(b2, aih[p]);
            }
            #pragma unroll
            for (int nb = 0; nb < 4; ++nb) {
                u32 off = SWZ64((u32)(((kb << 4) + (lane & 15)) * 64 + (nb << 4)));
                u32 Bvrh[2], Bvrl[2], Bvih[2], Bvil[2];
                ldmx2t(Bvrh, uvb + off);
                ldmx2t(Bvrl, uvb + VB + off);
                ldmx2t(Bvih, uvb + 2 * VB + off);
                ldmx2t(Bvil, uvb + 3 * VB + off);
                u32 Bvnh[2] = { Bvih[0] ^ NEGS, Bvih[1] ^ NEGS };
                u32 Bvnl[2] = { Bvil[0] ^ NEGS, Bvil[1] ^ NEGS };
                mma16816(accR[nb], arh, Bvrh);
                mma16816(accR[nb], arh, Bvrl);
                mma16816(accR[nb], arl, Bvrh);
                mma16816(accR[nb], aih, Bvnh);
                mma16816(accR[nb], aih, Bvnl);
                mma16816(accR[nb], ail, Bvnh);
                mma16816(accI[nb], arh, Bvih);
                mma16816(accI[nb], arh, Bvil);
                mma16816(accI[nb], arl, Bvih);
                mma16816(accI[nb], aih, Bvrh);
                mma16816(accI[nb], aih, Bvrl);
                mma16816(accI[nb], ail, Bvrh);
            }
        }
        // stash prefetched V into the other buffer
        if (c < 15) {
            char* nvb = sm + ((c + 1) & 1) * (4 * VB);
            #pragma unroll
            for (int it = 0; it < 4; ++it) {
                int k = kr0 + (it << 4);
                st_split2v(nvb, nvb + VB, k, dp, pVr[it]);
                st_split2v(nvb + 2 * VB, nvb + 3 * VB, k, dp, pVi[it]);
            }
        }
        __syncthreads();
    }

    // ---- epilogue: out[2][64][1024][64], imag at +4194304 ----
    #pragma unroll
    for (int hf = 0; hf < 2; ++hf) {
        int row = (hf == 0) ? gr0 : gr1;
        size_t ob = ((size_t)((bh << 10) + row) << 6) + (dh << 5) + tg * 2;
        #pragma unroll
        for (int nb = 0; nb < 4; ++nb) {
            *(float2*)(out + ob + nb * 8) =
                make_float2(accR[nb][hf * 2], accR[nb][hf * 2 + 1]);
            *(float2*)(out + ob + nb * 8 + 4194304) =
                make_float2(accI[nb][hf * 2], accI[nb][hf * 2 + 1]);
        }
    }
}

extern "C" void kernel_launch(void* const* d_in, const int* in_sizes, int n_in,
                              void* d_out, int out_size)
{
    (void)in_sizes; (void)n_in; (void)out_size;
    const float* qr = (const float*)d_in[0];
    const float* qi = (const float*)d_in[1];
    const float* kr = (const float*)d_in[2];
    const float* ki = (const float*)d_in[3];
    const float* vr = (const float*)d_in[4];
    const float* vi = (const float*)d_in[5];
    float* out = (float*)d_out;

    const int smem_qk = 4 * TB16 + 2 * 4 * TB8;   // 131072
    const int smem_av = 2 * 4 * VB;                // 32768
    cudaFuncSetAttribute(qk_kernel, cudaFuncAttributeMaxDynamicSharedMemorySize, smem_qk);
    cudaFuncSetAttribute(av_kernel, cudaFuncAttributeMaxDynamicSharedMemorySize, smem_av);

    qk_kernel<<<dim3(2, 8, 64), 256, smem_qk>>>(qr, qi, kr, ki);
    minmax_kernel<<<256, 256>>>();
    av_kernel<<<dim3(2, 8, 64), 256, smem_av>>>(vr, vi, out);
}

// round 10
// speedup vs baseline: 1.4376x; 1.4376x over previous
#include <cuda_runtime.h>
#include <cuda_bf16.h>
#include <cstdint>

// Complex attention, mma.sync bf16 3-term split + Gauss 3-mult complex GEMMs.
// B=8 H=8 S=1024 D=64.
// K1: attn=(q/8).k -> spill + per-(row,ktile) mag^2 min/max
// K2: row min/max reduce
// K3: normalize(attn) @ v
// Gauss: P1=xr*yr, P2=xi*yi, P3=(xr+xi)*(yr+yi); re=P1-P2, im=P3-P1-P2.

#define NKT 16
typedef unsigned long long u64;
typedef uint32_t u32;

__device__ float g_ar[(size_t)64 * 1024 * 1024];   // 256 MB
__device__ float g_ai[(size_t)64 * 1024 * 1024];   // 256 MB
__device__ float g_pmin[64 * 1024 * NKT];
__device__ float g_pmax[64 * 1024 * NKT];
__device__ float g_mn[64 * 1024];
__device__ float g_inv[64 * 1024];

__device__ __forceinline__ u32 smem_u32(const void* p) {
    u32 a;
    asm("{ .reg .u64 t; cvta.to.shared.u64 t, %1; cvt.u32.u64 %0, t; }"
        : "=r"(a) : "l"(p));
    return a;
}

#define SW128(x) ((x) ^ (((x) >> 3) & 0x70))
#define TB8 8192

__device__ __forceinline__ void ldmx4(u32* r, u32 a) {
    asm volatile("ldmatrix.sync.aligned.m8n8.x4.shared.b16 {%0,%1,%2,%3}, [%4];"
        : "=r"(r[0]), "=r"(r[1]), "=r"(r[2]), "=r"(r[3]) : "r"(a));
}
__device__ __forceinline__ void ldmx2(u32* r, u32 a) {
    asm volatile("ldmatrix.sync.aligned.m8n8.x2.shared.b16 {%0,%1}, [%2];"
        : "=r"(r[0]), "=r"(r[1]) : "r"(a));
}
__device__ __forceinline__ void ldmx2t(u32* r, u32 a) {
    asm volatile("ldmatrix.sync.aligned.m8n8.x2.trans.shared.b16 {%0,%1}, [%2];"
        : "=r"(r[0]), "=r"(r[1]) : "r"(a));
}
__device__ __forceinline__ void mma16816(float* c, const u32* a, const u32* b) {
    asm volatile("mma.sync.aligned.m16n8k16.row.col.f32.bf16.bf16.f32 "
        "{%0,%1,%2,%3}, {%4,%5,%6,%7}, {%8,%9}, {%0,%1,%2,%3};"
        : "+f"(c[0]), "+f"(c[1]), "+f"(c[2]), "+f"(c[3])
        : "r"(a[0]), "r"(a[1]), "r"(a[2]), "r"(a[3]), "r"(b[0]), "r"(b[1]));
}

// fp32 pair -> bf16 hi/lo pairs, SW128 layout (128B rows).
__device__ __forceinline__ void st_split2(char* hi, char* lo, int row, int cp, float2 v) {
    __nv_bfloat162 h = __float22bfloat162_rn(v);
    float2 hf = __bfloat1622float2(h);
    __nv_bfloat162 l = __float22bfloat162_rn(make_float2(v.x - hf.x, v.y - hf.y));
    u32 off = SW128((u32)(row * 128 + cp * 4));
    *(u32*)(hi + off) = *(u32*)&h;
    *(u32*)(lo + off) = *(u32*)&l;
}

// 3-term split product accumulate: P += x*y (hh, hl, lh)
#define MMA3(P, Ah, Al, Bh, Bl) \
    do { mma16816(P, Ah, Bh); mma16816(P, Ah, Bl); mma16816(P, Al, Bh); } while (0)

// ---------------------------------------------------------------------------
// K1: QK. CTA tile 64q x 64k. 8 warps (4m x 2n), warp tile 16q x 32k.
// smem: 6 arrays A (qr,qi,qs hi/lo) + 6 arrays B = 12 x 8KB = 96KB.
// ---------------------------------------------------------------------------
__global__ __launch_bounds__(256, 2) void qk_kernel(
    const float* __restrict__ qr, const float* __restrict__ qi,
    const float* __restrict__ kr, const float* __restrict__ ki)
{
    extern __shared__ __align__(128) char sm[];
    char* s_q[6];   // qr_h, qr_l, qi_h, qi_l, qs_h, qs_l
    char* s_k[6];
    #pragma unroll
    for (int a = 0; a < 6; ++a) { s_q[a] = sm + a * TB8; s_k[a] = sm + (6 + a) * TB8; }
    __shared__ float sMin[64][2], sMax[64][2];

    const int tid = threadIdx.x, wid = tid >> 5, lane = tid & 31;
    const int kt = blockIdx.x, qt = blockIdx.y, bh = blockIdx.z;
    const int cp = tid & 31, r0 = tid >> 5;

    // ---- fill ----
    {
        const size_t qbase = ((size_t)((bh << 10) + (qt << 6))) << 6;
        const size_t kbase = ((size_t)((bh << 10) + (kt << 6))) << 6;
        #pragma unroll
        for (int it = 0; it < 8; ++it) {
            int row = r0 + (it << 3);
            float2 a = *(const float2*)(qr + qbase + (row << 6) + cp * 2);
            float2 b = *(const float2*)(qi + qbase + (row << 6) + cp * 2);
            a.x *= 0.125f; a.y *= 0.125f;
            b.x *= 0.125f; b.y *= 0.125f;
            float2 s = make_float2(a.x + b.x, a.y + b.y);
            st_split2(s_q[0], s_q[1], row, cp, a);
            st_split2(s_q[2], s_q[3], row, cp, b);
            st_split2(s_q[4], s_q[5], row, cp, s);
            float2 c = *(const float2*)(kr + kbase + (row << 6) + cp * 2);
            float2 d = *(const float2*)(ki + kbase + (row << 6) + cp * 2);
            float2 e = make_float2(c.x + d.x, c.y + d.y);
            st_split2(s_k[0], s_k[1], row, cp, c);
            st_split2(s_k[2], s_k[3], row, cp, d);
            st_split2(s_k[4], s_k[5], row, cp, e);
        }
    }
    __syncthreads();

    // ---- compute ----
    const int wm = wid >> 1, wn = wid & 1;
    const int g = lane >> 2, tg = lane & 3;
    float P1[4][4] = {}, P2[4][4] = {}, P3[4][4] = {};

    u32 uq[6], uk[6];
    #pragma unroll
    for (int a = 0; a < 6; ++a) { uq[a] = smem_u32(s_q[a]); uk[a] = smem_u32(s_k[a]); }

    const u32 a_row = (u32)(wm * 16 + (lane & 15));
    const u32 a_cb  = (u32)((lane >> 4) * 16);
    const u32 b_row = (u32)(wn * 32 + (lane & 7));
    const u32 b_cb  = (u32)(((lane >> 3) & 1) * 16);

    #pragma unroll
    for (int kb = 0; kb < 4; ++kb) {
        u32 A[6][4];
        {
            u32 off = SW128(a_row * 128 + kb * 32 + a_cb);
            #pragma unroll
            for (int a = 0; a < 6; ++a) ldmx4(A[a], uq[a] + off);
        }
        #pragma unroll
        for (int nb = 0; nb < 4; ++nb) {
            u32 off = SW128((b_row + nb * 8) * 128 + kb * 32 + b_cb);
            u32 B[6][2];
            #pragma unroll
            for (int a = 0; a < 6; ++a) ldmx2(B[a], uk[a] + off);
            MMA3(P1[nb], A[0], A[1], B[0], B[1]);
            MMA3(P2[nb], A[2], A[3], B[2], B[3]);
            MMA3(P3[nb], A[4], A[5], B[4], B[5]);
        }
    }

    // ---- epilogue: re = P1-P2, im = P3-P1-P2; store + row min/max(m^2) ----
    #pragma unroll
    for (int hf = 0; hf < 2; ++hf) {
        int rl = wm * 16 + hf * 8 + g;
        size_t ab = (((size_t)((bh << 10) + (qt << 6) + rl)) << 10)
                  + (kt << 6) + wn * 32 + tg * 2;
        float mn = 3.4e38f, mx = 0.0f;
        #pragma unroll
        for (int nb = 0; nb < 4; ++nb) {
            float x0 = P1[nb][hf * 2] - P2[nb][hf * 2];
            float x1 = P1[nb][hf * 2 + 1] - P2[nb][hf * 2 + 1];
            float y0 = P3[nb][hf * 2] - P1[nb][hf * 2] - P2[nb][hf * 2];
            float y1 = P3[nb][hf * 2 + 1] - P1[nb][hf * 2 + 1] - P2[nb][hf * 2 + 1];
            *(float2*)(g_ar + ab + nb * 8) = make_float2(x0, x1);
            *(float2*)(g_ai + ab + nb * 8) = make_float2(y0, y1);
            float m0 = x0 * x0 + y0 * y0, m1 = x1 * x1 + y1 * y1;
            mn = fminf(mn, fminf(m0, m1));
            mx = fmaxf(mx, fmaxf(m0, m1));
        }
        mn = fminf(mn, __shfl_xor_sync(0xffffffffu, mn, 1));
        mn = fminf(mn, __shfl_xor_sync(0xffffffffu, mn, 2));
        mx = fmaxf(mx, __shfl_xor_sync(0xffffffffu, mx, 1));
        mx = fmaxf(mx, __shfl_xor_sync(0xffffffffu, mx, 2));
        if (tg == 0) { sMin[rl][wn] = mn; sMax[rl][wn] = mx; }
    }
    __syncthreads();
    if (tid < 64) {
        float mn = fminf(sMin[tid][0], sMin[tid][1]);
        float mx = fmaxf(sMax[tid][0], sMax[tid][1]);
        int row = (qt << 6) + tid;
        g_pmin[((bh << 10) + row) * NKT + kt] = mn;
        g_pmax[((bh << 10) + row) * NKT + kt] = mx;
    }
}

// ---------------------------------------------------------------------------
// K2: reduce 16 partials/row -> mn = sqrt(min m2), inv = 1/(mx - mn).
// ---------------------------------------------------------------------------
__global__ void minmax_kernel()
{
    int r = blockIdx.x * 256 + threadIdx.x;   // 65536 rows
    float mn2 = g_pmin[r * NKT], mx2 = g_pmax[r * NKT];
    #pragma unroll
    for (int t = 1; t < NKT; t++) {
        mn2 = fminf(mn2, g_pmin[r * NKT + t]);
        mx2 = fmaxf(mx2, g_pmax[r * NKT + t]);
    }
    float mnv = sqrtf(mn2), mxv = sqrtf(mx2);
    g_mn[r] = mnv;
    g_inv[r] = 1.0f / (mxv - mnv);
}

// ---------------------------------------------------------------------------
// K3: AV. CTA tile 64q x 64d; 16 k-chunks of 64. 8 warps (4m x 2n),
// warp tile 16q x 32d. A = normalized attn (ar,ai,as), V natural [k][d]
// (vr,vi,vs), B frags via ldmatrix.x2.trans. Gauss accumulate P1,P2,P3.
// f = inv - (mn*inv)*rsqrt(m2)
// ---------------------------------------------------------------------------
__global__ __launch_bounds__(256, 2) void av_kernel(
    const float* __restrict__ vr, const float* __restrict__ vi,
    float* __restrict__ out)
{
    extern __shared__ __align__(128) char sm[];
    char* s_a[6];   // ar_h, ar_l, ai_h, ai_l, as_h, as_l  [64q][64k]
    char* s_v[6];   // vr_h, vr_l, vi_h, vi_l, vs_h, vs_l  [64k][64d]
    #pragma unroll
    for (int a = 0; a < 6; ++a) { s_a[a] = sm + a * TB8; s_v[a] = sm + (6 + a) * TB8; }
    __shared__ float smn[64], sinv[64];

    const int tid = threadIdx.x, wid = tid >> 5, lane = tid & 31;
    const int qt = blockIdx.x, bh = blockIdx.y;
    const int cp = tid & 31, r0 = tid >> 5;

    if (tid < 64) {
        int r = (bh << 10) + (qt << 6) + tid;
        float mnv = g_mn[r], invv = g_inv[r];
        sinv[tid] = invv;
        smn[tid] = mnv * invv;   // pre-multiplied
    }
    __syncthreads();

    const int wm = wid >> 1, wn = wid & 1;
    const int g = lane >> 2, tg = lane & 3;
    float P1[4][4] = {}, P2[4][4] = {}, P3[4][4] = {};

    u32 ua[6], uv[6];
    #pragma unroll
    for (int a = 0; a < 6; ++a) { ua[a] = smem_u32(s_a[a]); uv[a] = smem_u32(s_v[a]); }

    const u32 a_row = (u32)(wm * 16 + (lane & 15));
    const u32 a_cb  = (u32)((lane >> 4) * 16);
    const u32 bt_row = (u32)(lane & 15);     // + kb*16
    const u32 bt_cb  = (u32)(wn * 64);       // bytes; + nb*16

    const size_t abase = ((size_t)((bh << 10) + (qt << 6))) << 10;
    const size_t vbase = ((size_t)(bh << 10)) << 6;

    for (int c = 0; c < 16; ++c) {
        // A fill: normalized attn [64q][64k]
        #pragma unroll
        for (int it = 0; it < 8; ++it) {
            int row = r0 + (it << 3);
            size_t ao = abase + ((size_t)row << 10) + (c << 6) + cp * 2;
            float2 a = *(const float2*)(g_ar + ao);
            float2 b = *(const float2*)(g_ai + ao);
            float invv = sinv[row], mni = smn[row];
            float f0 = invv - mni * rsqrtf(a.x * a.x + b.x * b.x);
            float f1 = invv - mni * rsqrtf(a.y * a.y + b.y * b.y);
            float2 an = make_float2(a.x * f0, a.y * f1);
            float2 bn = make_float2(b.x * f0, b.y * f1);
            float2 sn = make_float2(an.x + bn.x, an.y + bn.y);
            st_split2(s_a[0], s_a[1], row, cp, an);
            st_split2(s_a[2], s_a[3], row, cp, bn);
            st_split2(s_a[4], s_a[5], row, cp, sn);
        }
        // V fill: natural [64k][64d]
        #pragma unroll
        for (int it = 0; it < 8; ++it) {
            int krow = r0 + (it << 3);
            size_t vo = vbase + ((size_t)((c << 6) + krow) << 6) + cp * 2;
            float2 x = *(const float2*)(vr + vo);
            float2 y = *(const float2*)(vi + vo);
            float2 s = make_float2(x.x + y.x, x.y + y.y);
            st_split2(s_v[0], s_v[1], krow, cp, x);
            st_split2(s_v[2], s_v[3], krow, cp, y);
            st_split2(s_v[4], s_v[5], krow, cp, s);
        }
        __syncthreads();

        #pragma unroll
        for (int kb = 0; kb < 4; ++kb) {
            u32 A[6][4];
            {
                u32 off = SW128(a_row * 128 + kb * 32 + a_cb);
                #pragma unroll
                for (int a = 0; a < 6; ++a) ldmx4(A[a], ua[a] + off);
            }
            #pragma unroll
            for (int nb = 0; nb < 4; ++nb) {
                u32 off = SW128((bt_row + kb * 16) * 128 + bt_cb + nb * 16);
                u32 B[6][2];
                #pragma unroll
                for (int a = 0; a < 6; ++a) ldmx2t(B[a], uv[a] + off);
                MMA3(P1[nb], A[0], A[1], B[0], B[1]);
                MMA3(P2[nb], A[2], A[3], B[2], B[3]);
                MMA3(P3[nb], A[4], A[5], B[4], B[5]);
            }
        }
        __syncthreads();
    }

    // ---- epilogue: out[2][64][1024][64], imag at +4194304 ----
    #pragma unroll
    for (int hf = 0; hf < 2; ++hf) {
        int row = (qt << 6) + wm * 16 + hf * 8 + g;
        size_t ob = ((size_t)((bh << 10) + row) << 6) + wn * 32 + tg * 2;
        #pragma unroll
        for (int nb = 0; nb < 4; ++nb) {
            float x0 = P1[nb][hf * 2] - P2[nb][hf * 2];
            float x1 = P1[nb][hf * 2 + 1] - P2[nb][hf * 2 + 1];
            float y0 = P3[nb][hf * 2] - P1[nb][hf * 2] - P2[nb][hf * 2];
            float y1 = P3[nb][hf * 2 + 1] - P1[nb][hf * 2 + 1] - P2[nb][hf * 2 + 1];
            *(float2*)(out + ob + nb * 8) = make_float2(x0, x1);
            *(float2*)(out + ob + nb * 8 + 4194304) = make_float2(y0, y1);
        }
    }
}

extern "C" void kernel_launch(void* const* d_in, const int* in_sizes, int n_in,
                              void* d_out, int out_size)
{
    (void)in_sizes; (void)n_in; (void)out_size;
    const float* qr = (const float*)d_in[0];
    const float* qi = (const float*)d_in[1];
    const float* kr = (const float*)d_in[2];
    const float* ki = (const float*)d_in[3];
    const float* vr = (const float*)d_in[4];
    const float* vi = (const float*)d_in[5];
    float* out = (float*)d_out;

    const int smem = 12 * TB8;   // 98304
    cudaFuncSetAttribute(qk_kernel, cudaFuncAttributeMaxDynamicSharedMemorySize, smem);
    cudaFuncSetAttribute(av_kernel, cudaFuncAttributeMaxDynamicSharedMemorySize, smem);

    qk_kernel<<<dim3(16, 16, 64), 256, smem>>>(qr, qi, kr, ki);
    minmax_kernel<<<256, 256>>>();
    av_kernel<<<dim3(16, 64), 256, smem>>>(vr, vi, out);
}